// round 9
// baseline (speedup 1.0000x reference)
#include <cuda_runtime.h>
#include <cuda_bf16.h>
#include <cstdint>

// AbsolutePositionEncoding: out[b][s][e] = E[s/8][e], b<64, s<2048, e<256 (fp32)
// Only objects 0..255 referenced. Pure broadcast-write: 128 MiB stores.
//
// R8 = R7 resubmit (container infra failed; kernel never ran).
// Write path switched from scalar STG.128 (capped ~3.5 TB/s by LSU/store
// credits, per R5/R6 profiles) to TMA bulk stores (cp.async.bulk, SASS UBLKCP).
// Each block stages its object's 8 KB pattern (row repeated 8x) in SMEM once,
// then fires 16 engine-side 8 KB bulk stores (one per batch position, 2 MB
// stride). Fire-and-forget engine transfers fill the HBM write pipeline far
// deeper than register stores.

__global__ __launch_bounds__(256, 8)
void ape_tma_kernel(const float4* __restrict__ E4, float4* __restrict__ out4) {
    __shared__ alignas(128) float4 buf[512];   // 8 KB: 8 tokens x 64 f4

    const int obj = blockIdx.x;                // 0..255
    const int t   = threadIdx.x;               // 0..255
    const int b0  = blockIdx.y * 16;           // starting batch: 0,16,32,48

    // One float4 of the row per thread (lane repeats mod 64); fill both halves.
    const float4 v = E4[obj * 64 + (t & 63)];
    buf[t]       = v;
    buf[t + 256] = v;

    __syncthreads();
    // Order generic SMEM writes before async-proxy (TMA) reads.
    asm volatile("fence.proxy.async.shared::cta;" ::: "memory");

    if (t == 0) {
        uint32_t saddr = (uint32_t)__cvta_generic_to_shared(buf);
        // GMEM byte geometry: batch stride = 131072 f4 * 16 B = 2 MiB;
        // object span = obj*512 f4 * 16 B = obj * 8 KiB, length 8 KiB.
        const char* gbase = (const char*)out4
                          + (size_t)b0 * 2097152ull
                          + (size_t)obj * 8192ull;
        #pragma unroll
        for (int b = 0; b < 16; ++b) {
            uint64_t g = (uint64_t)(gbase + (size_t)b * 2097152ull);
            asm volatile(
                "cp.async.bulk.global.shared::cta.bulk_group [%0], [%1], %2;"
                :: "l"(g), "r"(saddr), "r"(8192) : "memory");
        }
        asm volatile("cp.async.bulk.commit_group;" ::: "memory");
        // Must complete before CTA exit (SMEM source + cross-kernel visibility).
        asm volatile("cp.async.bulk.wait_group 0;" ::: "memory");
    }
}

extern "C" void kernel_launch(void* const* d_in, const int* in_sizes, int n_in,
                              void* d_out, int out_size) {
    // d_in[0] = x (unused), d_in[1] = E_absolute_position [512, 256] fp32
    const float4* E4 = (const float4*)d_in[1];
    float4* out4 = (float4*)d_out;
    dim3 grid(256, 4);
    ape_tma_kernel<<<grid, 256>>>(E4, out4);
}